// round 2
// baseline (speedup 1.0000x reference)
#include <cuda_runtime.h>
#include <cuda_bf16.h>
#include <cstdint>

#define NB   32
#define CC   256
#define HHW  56
#define HW   3136      // 56*56
#define MTOT 100352    // 32*3136
#define K3   2304      // 256*9

// ---------------- device global scratch (no allocations allowed) ----------------
__device__ __align__(256) __nv_bfloat16 g_S[(size_t)MTOT * CC];    // sign activations, NHWC (reused stage1/2)
__device__ __align__(256) __nv_bfloat16 g_Bw3[(size_t)CC * K3];    // binarized 3x3 weights [o][tap][c]
__device__ __align__(256) __nv_bfloat16 g_Bw1[(size_t)CC * CC];    // binarized 1x1 weights [o][c]
__device__ float g_scale3[CC];
__device__ float g_scale1[CC];
__device__ __align__(256) float g_conv[(size_t)MTOT * CC];         // conv output, NHWC (reused)
__device__ __align__(256) float g_xmid[(size_t)MTOT * CC];         // stage-1 result, NHWC
__device__ float g_part[128 * CC * 2];                             // BN partial sums
__device__ float g_bnA[CC];                                        // folded BN scale
__device__ float g_bnB[CC];                                        // folded BN shift

__device__ __forceinline__ float sgnf(float v) {
    return (v > 0.f) ? 1.f : ((v < 0.f) ? -1.f : 0.f);
}

// ---------------- weight prep ----------------
__global__ void wprep3_kernel(const float* __restrict__ w) {
    int o = blockIdx.x, tid = threadIdx.x;
    float s = 0.f;
    for (int k = tid; k < K3; k += 256) {
        float v = w[o * K3 + k];
        int c = k / 9, t = k - c * 9;
        g_Bw3[o * K3 + t * 256 + c] = __float2bfloat16(sgnf(v));
        s += fabsf(v);
    }
    __shared__ float red[256];
    red[tid] = s; __syncthreads();
    for (int st = 128; st > 0; st >>= 1) { if (tid < st) red[tid] += red[tid + st]; __syncthreads(); }
    if (tid == 0) g_scale3[o] = red[0] / (float)K3;
}

__global__ void wprep1_kernel(const float* __restrict__ w) {
    int o = blockIdx.x, tid = threadIdx.x;
    float v = w[o * 256 + tid];
    g_Bw1[o * 256 + tid] = __float2bfloat16(sgnf(v));
    __shared__ float red[256];
    red[tid] = fabsf(v); __syncthreads();
    for (int st = 128; st > 0; st >>= 1) { if (tid < st) red[tid] += red[tid + st]; __syncthreads(); }
    if (tid == 0) g_scale1[o] = red[0] / 256.f;
}

// ---------------- sign(x + b1_1): NCHW -> NHWC bf16 via smem transpose ----------------
__global__ void sign_in_kernel(const float* __restrict__ x, const float* __restrict__ b1) {
    __shared__ float xs[64][65];
    int hw0 = blockIdx.x * 64, c0 = blockIdx.y * 64, n = blockIdx.z;
    int tid = threadIdx.x;
#pragma unroll
    for (int i = 0; i < 16; i++) {
        int e = tid + 256 * i;
        int ci = e >> 6, hwi = e & 63;
        xs[ci][hwi] = x[((size_t)(n * CC + c0 + ci)) * HW + hw0 + hwi];
    }
    __syncthreads();
    int ci = tid & 63;
    float b = b1[c0 + ci];
#pragma unroll
    for (int i = 0; i < 16; i++) {
        int e = tid + 256 * i;
        int hwi = e >> 6;
        float v = xs[ci][hwi] + b;
        g_S[((size_t)(n * HW + hw0 + hwi)) * CC + c0 + ci] = __float2bfloat16(sgnf(v));
    }
}

// ---------------- mma helpers ----------------
__device__ __forceinline__ void ldsm_x4(uint32_t (&r)[4], uint32_t addr) {
    asm volatile("ldmatrix.sync.aligned.m8n8.x4.shared.b16 {%0,%1,%2,%3}, [%4];\n"
                 : "=r"(r[0]), "=r"(r[1]), "=r"(r[2]), "=r"(r[3]) : "r"(addr));
}
__device__ __forceinline__ void mma16816(float (&d)[4], const uint32_t (&a)[4], const uint32_t* b) {
    asm volatile("mma.sync.aligned.m16n8k16.row.col.f32.bf16.bf16.f32 "
                 "{%0,%1,%2,%3}, {%4,%5,%6,%7}, {%8,%9}, {%0,%1,%2,%3};\n"
                 : "+f"(d[0]), "+f"(d[1]), "+f"(d[2]), "+f"(d[3])
                 : "r"(a[0]), "r"(a[1]), "r"(a[2]), "r"(a[3]), "r"(b[0]), "r"(b[1]));
}

// ---------------- implicit-GEMM binarized conv (TAPS=9: 3x3 pad1; TAPS=1: 1x1) ----------------
// A = g_S (NHWC bf16, +-1), B = binarized weights [o][tap][c], C = g_conv (NHWC f32, scaled)
template <int TAPS>
__global__ void __launch_bounds__(256, 1) conv_mma_kernel() {
    __shared__ __align__(16) char smem[2 * 128 * 72 * 2];
    __nv_bfloat16* As = (__nv_bfloat16*)smem;
    __nv_bfloat16* Bs = (__nv_bfloat16*)(smem + 128 * 72 * 2);

    const __nv_bfloat16* __restrict__ Bw = (TAPS == 9) ? g_Bw3 : g_Bw1;
    const float* __restrict__ scale = (TAPS == 9) ? g_scale3 : g_scale1;

    int tid = threadIdx.x, lane = tid & 31, warp = tid >> 5;
    int wm = warp >> 2, wn = warp & 3;           // 2 warps along M, 4 along N
    int m0 = blockIdx.x * 128, o0 = blockIdx.y * 128;

    float acc[4][4][4];
#pragma unroll
    for (int a = 0; a < 4; a++)
#pragma unroll
        for (int b = 0; b < 4; b++)
#pragma unroll
            for (int c = 0; c < 4; c++) acc[a][b][c] = 0.f;

    const int ldB = TAPS * 256;
    int lr = tid >> 1;                 // 0..127 (tile row)
    int lc = (tid & 1) * 32;           // bf16 element offset within row

    for (int t = 0; t < TAPS; t++) {
        int dy = (TAPS == 9) ? (t / 3 - 1) : 0;
        int dx = (TAPS == 9) ? (t % 3 - 1) : 0;
        int m = m0 + lr;
        int n = m / HW; int hw = m - n * HW;
        int h = hw / HHW; int w = hw - h * HHW;
        int hh = h + dy, ww = w + dx;
        bool valid = ((unsigned)hh < HHW) && ((unsigned)ww < HHW);
        const __nv_bfloat16* srcA = g_S + ((size_t)(n * HW + hh * HHW + ww)) * 256 + lc;
        const __nv_bfloat16* srcB = Bw + (size_t)(o0 + lr) * ldB + t * 256 + lc;

        for (int kc = 0; kc < 256; kc += 64) {
            uint4 z4 = make_uint4(0, 0, 0, 0);
            uint4* dA = (uint4*)(As + lr * 72 + lc);
            const uint4* sA = (const uint4*)(srcA + kc);
            uint4* dB = (uint4*)(Bs + lr * 72 + lc);
            const uint4* sB = (const uint4*)(srcB + kc);
#pragma unroll
            for (int i = 0; i < 4; i++) dA[i] = valid ? sA[i] : z4;
#pragma unroll
            for (int i = 0; i < 4; i++) dB[i] = sB[i];
            __syncthreads();

#pragma unroll
            for (int kk = 0; kk < 64; kk += 16) {
                uint32_t a[4][4];
#pragma unroll
                for (int mf = 0; mf < 4; mf++) {
                    int row = wm * 64 + mf * 16 + (lane & 15);
                    int col = kk + ((lane >> 4) << 3);
                    ldsm_x4(a[mf], (uint32_t)__cvta_generic_to_shared(As + row * 72 + col));
                }
                uint32_t bq[2][4];
#pragma unroll
                for (int g = 0; g < 2; g++) {
                    int row = wn * 32 + g * 16 + (lane & 7) + (((lane >> 4) & 1) << 3);
                    int col = kk + (((lane >> 3) & 1) << 3);
                    ldsm_x4(bq[g], (uint32_t)__cvta_generic_to_shared(Bs + row * 72 + col));
                }
#pragma unroll
                for (int mf = 0; mf < 4; mf++)
#pragma unroll
                    for (int nf = 0; nf < 4; nf++)
                        mma16816(acc[mf][nf], a[mf], &bq[nf >> 1][(nf & 1) * 2]);
            }
            __syncthreads();
        }
    }

    // epilogue: stage through smem -> coalesced NHWC stores, apply per-o scale
    float* Cs = (float*)smem;
#pragma unroll 1
    for (int j = 0; j < 4; j++) {
        if (wn == j) {
#pragma unroll
            for (int mf = 0; mf < 4; mf++)
#pragma unroll
                for (int nf = 0; nf < 4; nf++) {
                    int row = wm * 64 + mf * 16 + (lane >> 2);
                    int col = nf * 8 + (lane & 3) * 2;
                    Cs[row * 33 + col]           = acc[mf][nf][0];
                    Cs[row * 33 + col + 1]       = acc[mf][nf][1];
                    Cs[(row + 8) * 33 + col]     = acc[mf][nf][2];
                    Cs[(row + 8) * 33 + col + 1] = acc[mf][nf][3];
                }
        }
        __syncthreads();
#pragma unroll
        for (int i = 0; i < 16; i++) {
            int e = tid + 256 * i;
            int row = e >> 5, col = e & 31;
            int o = o0 + j * 32 + col;
            g_conv[(size_t)(m0 + row) * 256 + o] = Cs[row * 33 + col] * scale[o];
        }
        __syncthreads();
    }
}

// ---------------- per-channel BN partial sums over NHWC conv output ----------------
__global__ void red_part_kernel() {
    int b = blockIdx.x;        // 128 blocks
    int c = threadIdx.x;       // 256 channels
    float s1 = 0.f, s2 = 0.f;
    int base = b * 784;
    for (int r = 0; r < 784; r++) {
        float v = g_conv[((size_t)(base + r)) * CC + c];
        s1 += v; s2 += v * v;
    }
    g_part[(b * CC + c) * 2]     = s1;
    g_part[(b * CC + c) * 2 + 1] = s2;
}

__global__ void stats_kernel(const float* __restrict__ gamma, const float* __restrict__ beta) {
    int c = threadIdx.x;
    float s1 = 0.f, s2 = 0.f;
    for (int b = 0; b < 128; b++) {
        s1 += g_part[(b * CC + c) * 2];
        s2 += g_part[(b * CC + c) * 2 + 1];
    }
    float mean = s1 / (float)MTOT;
    float var  = s2 / (float)MTOT - mean * mean;
    float inv  = rsqrtf(var + 1e-5f);
    g_bnA[c] = gamma[c] * inv;
    g_bnB[c] = beta[c] - mean * gamma[c] * inv;
}

// ---------------- stage-1 tail: BN + residual + bias + PReLU + bias; emit x_mid & sign for stage 2 ----------------
__global__ void fuse1_kernel(const float* __restrict__ x, const float* __restrict__ b12,
                             const float* __restrict__ a1, const float* __restrict__ b13,
                             const float* __restrict__ b21) {
    __shared__ float xs[64][65];
    int hw0 = blockIdx.x * 64, c0 = blockIdx.y * 64, n = blockIdx.z;
    int tid = threadIdx.x;
#pragma unroll
    for (int i = 0; i < 16; i++) {
        int e = tid + 256 * i;
        int ci = e >> 6, hwi = e & 63;
        xs[ci][hwi] = x[((size_t)(n * CC + c0 + ci)) * HW + hw0 + hwi];
    }
    __syncthreads();
    int ci = tid & 63, c = c0 + ci;
    float A = g_bnA[c], B = g_bnB[c];
    float vb12 = b12[c], va = a1[c], vb13 = b13[c], vb21 = b21[c];
#pragma unroll
    for (int i = 0; i < 16; i++) {
        int e = tid + 256 * i;
        int hwi = e >> 6;
        size_t idx = ((size_t)(n * HW + hw0 + hwi)) * CC + c;
        float y = xs[ci][hwi] + g_conv[idx] * A + B;
        y += vb12;
        y = (y >= 0.f) ? y : va * y;
        y += vb13;
        g_xmid[idx] = y;
        g_S[idx] = __float2bfloat16(sgnf(y + vb21));
    }
}

// ---------------- stage-2 tail: BN + residual + bias + PReLU + bias; NHWC -> NCHW out ----------------
__global__ void fuse2_kernel(const float* __restrict__ b22, const float* __restrict__ a2,
                             const float* __restrict__ b23, float* __restrict__ out) {
    __shared__ float ys[64][65];
    int hw0 = blockIdx.x * 64, c0 = blockIdx.y * 64, n = blockIdx.z;
    int tid = threadIdx.x;
    int ci = tid & 63, c = c0 + ci;
    float A = g_bnA[c], B = g_bnB[c];
    float vb22 = b22[c], va = a2[c], vb23 = b23[c];
#pragma unroll
    for (int i = 0; i < 16; i++) {
        int e = tid + 256 * i;
        int hwi = e >> 6;
        size_t idx = ((size_t)(n * HW + hw0 + hwi)) * CC + c;
        float y = g_conv[idx] * A + B + g_xmid[idx];
        y += vb22;
        y = (y >= 0.f) ? y : va * y;
        y += vb23;
        ys[ci][hwi] = y;
    }
    __syncthreads();
#pragma unroll
    for (int i = 0; i < 16; i++) {
        int e = tid + 256 * i;
        int c2 = e >> 6, hwi = e & 63;
        out[((size_t)(n * CC + c0 + c2)) * HW + hw0 + hwi] = ys[c2][hwi];
    }
}

// ---------------- launch ----------------
extern "C" void kernel_launch(void* const* d_in, const int* in_sizes, int n_in,
                              void* d_out, int out_size) {
    (void)in_sizes; (void)n_in; (void)out_size;
    const float* x     = (const float*)d_in[0];
    const float* b1_1  = (const float*)d_in[1];
    const float* w3x3  = (const float*)d_in[2];
    const float* bn1_g = (const float*)d_in[3];
    const float* bn1_b = (const float*)d_in[4];
    const float* b1_2  = (const float*)d_in[5];
    const float* a1    = (const float*)d_in[6];
    const float* b1_3  = (const float*)d_in[7];
    const float* b2_1  = (const float*)d_in[8];
    const float* wres  = (const float*)d_in[9];
    const float* bn2_g = (const float*)d_in[10];
    const float* bn2_b = (const float*)d_in[11];
    const float* b2_2  = (const float*)d_in[12];
    const float* a2    = (const float*)d_in[13];
    const float* b2_3  = (const float*)d_in[14];
    float* out = (float*)d_out;

    dim3 tileGrid(49, 4, 32);
    dim3 convGrid(784, 2);

    wprep3_kernel<<<256, 256>>>(w3x3);
    wprep1_kernel<<<256, 256>>>(wres);
    sign_in_kernel<<<tileGrid, 256>>>(x, b1_1);
    conv_mma_kernel<9><<<convGrid, 256>>>();
    red_part_kernel<<<128, 256>>>();
    stats_kernel<<<1, 256>>>(bn1_g, bn1_b);
    fuse1_kernel<<<tileGrid, 256>>>(x, b1_2, a1, b1_3, b2_1);
    conv_mma_kernel<1><<<convGrid, 256>>>();
    red_part_kernel<<<128, 256>>>();
    stats_kernel<<<1, 256>>>(bn2_g, bn2_b);
    fuse2_kernel<<<tileGrid, 256>>>(b2_2, a2, b2_3, out);
}